// round 16
// baseline (speedup 1.0000x reference)
#include <cuda_runtime.h>
#include <cuda_bf16.h>

// YOLO layer: x [B=16, C=255, 64, 64] fp32, anchors [3,2] fp32.
// pred = x.reshape(B, 3, 85, 64, 64).transpose(0,1,3,4,2)
// Outputs concatenated in d_out (float32):
//   boxes [B,3,64,64,4]  : 786,432    elems at offset 0
//   conf  [B,3,64,64]    : 196,608    elems at offset 786,432
//   cls   [B,3,64,64,80] : 15,728,640 elems at offset 983,040
//
// R15: combine the two independently-validated wins.
//  - R14 (committed, 19.8us): L2 residency inversion via createpolicy
//    cache_hint (input evict_first, output evict_last) -> DRAM/replay
//    87MB -> 77MB, write stream mostly L2-absorbed.
//  - R10 store linearization: cls stores in output-linear order so a
//    warp STG.128 covers 512B contiguous = 4 L2 line-touches instead
//    of 16 (R8/R14 mapping). With the output now L2-resident, store
//    line-touches hit L2 directly (L2=59% is the top pipe) -> 4x fewer.
// Structure: smem tile [85ch x 64pos] (float4 STS, pitch 68), then
// output-linear hinted stores for cls/boxes/conf in one block pass.
// sigmoid via MUFU.TANH: sig(x) = fma(0.5, tanh(0.5x), 0.5).

#define NT 256
#define TP 64
#define PITCH 68            // floats per smem row (16 f4 data + 1 f4 pad)
#define PITCH4 17           // float4s per row

__device__ __forceinline__ float sigf(float v) {
    float t;
    asm("tanh.approx.f32 %0, %1;" : "=f"(t) : "f"(v * 0.5f));
    return fmaf(0.5f, t, 0.5f);
}

__device__ __forceinline__ float4 ld_ef4(const float4* p, unsigned long long pol) {
    float4 v;
    asm("ld.global.nc.L2::cache_hint.v4.f32 {%0,%1,%2,%3}, [%4], %5;"
        : "=f"(v.x), "=f"(v.y), "=f"(v.z), "=f"(v.w) : "l"(p), "l"(pol));
    return v;
}
__device__ __forceinline__ void st_el4(float4* p, float4 v, unsigned long long pol) {
    asm volatile("st.global.L2::cache_hint.v4.f32 [%0], {%1,%2,%3,%4}, %5;"
                 :: "l"(p), "f"(v.x), "f"(v.y), "f"(v.z), "f"(v.w), "l"(pol)
                 : "memory");
}

__global__ __launch_bounds__(NT) void yolo_kernel(
    const float* __restrict__ x,
    const float* __restrict__ anchors,
    float* __restrict__ out)
{
    constexpr int A    = 3;
    constexpr int CH   = 85;
    constexpr int P    = 64 * 64;                     // 4096 positions per (b,a)
    constexpr int Btot = 16;
    constexpr int CONF_OFF = Btot * A * P * 4;        // 786432
    constexpr int CLS_OFF  = CONF_OFF + Btot * A * P; // 983040

    unsigned long long pol_ef, pol_el;
    asm("createpolicy.fractional.L2::evict_first.b64 %0, 1.0;" : "=l"(pol_ef));
    asm("createpolicy.fractional.L2::evict_last.b64 %0, 1.0;"  : "=l"(pol_el));

    __shared__ float4 tile4[CH * PITCH4];             // 85 x 17 float4 = 23.1 KB
    float* tile = reinterpret_cast<float*>(tile4);

    const int blk = blockIdx.x;
    const int ba  = blk >> 6;                         // 64 tiles per (b,a)
    const int p0  = (blk & 63) * TP;
    const int t   = threadIdx.x;

    // ---- Load: 85 ch x 16 float4, input-coalesced, evict_first hint ----
    const float4* xin4 = reinterpret_cast<const float4*>(
        x + (size_t)ba * CH * P + p0);                // p0 multiple of 64 -> aligned
    #pragma unroll
    for (int k = 0; k < 6; k++) {
        const int idx = t + k * NT;                   // 0..1535, need < 1360
        if (idx < CH * (TP / 4)) {
            const int c = idx >> 4;                   // channel
            const int q = idx & 15;
            tile4[c * PITCH4 + q] = ld_ef4(xin4 + c * (P / 4) + q, pol_ef);
        }
    }
    __syncthreads();

    // ---- cls: output-linear; tile region = 1280 contiguous float4.
    //      thread t writes f = t + 256k -> warp STG.128 = 512B contig
    //      = 4 L2 line-touches (vs 16 in the strided mapping). ----
    {
        float4* ocls4 = reinterpret_cast<float4*>(
            out + CLS_OFF + (size_t)(ba * P + p0) * 80);
        #pragma unroll
        for (int k = 0; k < 5; k++) {
            const int f = t + k * NT;                 // 0..1279
            const int p = f / 20;                     // position in tile (0..63)
            const int j = f - 20 * p;                 // float4 chunk (0..19)
            const int c = 5 + 4 * j;                  // channels c..c+3
            float4 o;
            o.x = sigf(tile[(c + 0) * PITCH + p]);
            o.y = sigf(tile[(c + 1) * PITCH + p]);
            o.z = sigf(tile[(c + 2) * PITCH + p]);
            o.w = sigf(tile[(c + 3) * PITCH + p]);
            st_el4(ocls4 + f, o, pol_el);
        }
    }

    // ---- boxes: threads 0..63, STG.128; warp = 512B contiguous ----
    if (t < TP) {
        const int a  = ba - (ba / A) * A;
        const float aw = __ldg(anchors + a * 2 + 0);
        const float ah = __ldg(anchors + a * 2 + 1);
        const int pg = p0 + t;
        float4 b;
        b.x = (sigf(tile[0 * PITCH + t]) + (float)(pg >> 6)) * (1.0f / 64.0f);
        b.y = (sigf(tile[1 * PITCH + t]) + (float)(pg & 63)) * (1.0f / 64.0f);
        b.z = __expf(tile[2 * PITCH + t]) * aw;
        b.w = __expf(tile[3 * PITCH + t]) * ah;
        st_el4(reinterpret_cast<float4*>(out) + ba * P + pg, b, pol_el);
    }
    // ---- conf: threads 64..79, LDS.128 + hinted STG.128 ----
    else if (t < TP + TP / 4) {
        const int q = t - TP;                         // 0..15
        float4 v = tile4[4 * PITCH4 + q];             // channel 4, float4-aligned
        v.x = sigf(v.x);
        v.y = sigf(v.y);
        v.z = sigf(v.z);
        v.w = sigf(v.w);
        st_el4(reinterpret_cast<float4*>(out + CONF_OFF + ba * P + p0) + q,
               v, pol_el);
    }
}

extern "C" void kernel_launch(void* const* d_in, const int* in_sizes, int n_in,
                              void* d_out, int out_size) {
    const float* x       = (const float*)d_in[0];
    const float* anchors = (const float*)d_in[1];
    float*       out     = (float*)d_out;
    yolo_kernel<<<3072, NT>>>(x, anchors, out);
}

// round 17
// speedup vs baseline: 1.2152x; 1.2152x over previous
#include <cuda_runtime.h>
#include <cuda_bf16.h>

// YOLO layer: x [B=16, C=255, 64, 64] fp32, anchors [3,2] fp32.
// pred = x.reshape(B, 3, 85, 64, 64).transpose(0,1,3,4,2)
// Outputs concatenated in d_out (float32):
//   boxes [B,3,64,64,4]  : 786,432    elems at offset 0
//   conf  [B,3,64,64]    : 196,608    elems at offset 786,432
//   cls   [B,3,64,64,80] : 15,728,640 elems at offset 983,040
//
// R16: R15 retry with only proven-fast components. Evidence so far:
//   - hinted WIDE loads (v4/v8 + cache_hint) = L1tex slow path
//     (R13: 32us, R15: 30us, both L1 ~70%). AVOID.
//   - hinted SCALAR loads + hinted v4 stores = fast (R14: 19.8us).
//   - output-linear store mapping (warp STG.128 = 512B contig = 4 L2
//     line-touches vs 16 strided) needs smem transpose (R10).
// This kernel: scalar evict_first hinted loads -> conflict-free scalar
// STS (pitch 65) -> output-linear v4 evict_last hinted stores.
// sigmoid via MUFU.TANH: sig(x) = fma(0.5, tanh(0.5x), 0.5).

#define NT 256
#define TP 64
#define PITCH 65            // scalar smem row pitch; bank = (c + p) % 32

__device__ __forceinline__ float sigf(float v) {
    float t;
    asm("tanh.approx.f32 %0, %1;" : "=f"(t) : "f"(v * 0.5f));
    return fmaf(0.5f, t, 0.5f);
}

__device__ __forceinline__ float ld_ef(const float* p, unsigned long long pol) {
    float v;
    asm("ld.global.nc.L2::cache_hint.f32 %0, [%1], %2;"
        : "=f"(v) : "l"(p), "l"(pol));
    return v;
}
__device__ __forceinline__ void st_el4(float4* p, float4 v, unsigned long long pol) {
    asm volatile("st.global.L2::cache_hint.v4.f32 [%0], {%1,%2,%3,%4}, %5;"
                 :: "l"(p), "f"(v.x), "f"(v.y), "f"(v.z), "f"(v.w), "l"(pol)
                 : "memory");
}

__global__ __launch_bounds__(NT) void yolo_kernel(
    const float* __restrict__ x,
    const float* __restrict__ anchors,
    float* __restrict__ out)
{
    constexpr int A    = 3;
    constexpr int CH   = 85;
    constexpr int P    = 64 * 64;                     // 4096 positions per (b,a)
    constexpr int Btot = 16;
    constexpr int CONF_OFF = Btot * A * P * 4;        // 786432
    constexpr int CLS_OFF  = CONF_OFF + Btot * A * P; // 983040

    unsigned long long pol_ef, pol_el;
    asm("createpolicy.fractional.L2::evict_first.b64 %0, 1.0;" : "=l"(pol_ef));
    asm("createpolicy.fractional.L2::evict_last.b64 %0, 1.0;"  : "=l"(pol_el));

    __shared__ float tile[CH * PITCH];                // 85 x 65 = 22.1 KB

    const int blk = blockIdx.x;
    const int ba  = blk >> 6;                         // 64 tiles per (b,a)
    const int p0  = (blk & 63) * TP;
    const int t   = threadIdx.x;

    // ---- Load: 5440 scalars, hinted evict_first; warp = 128B line;
    //      STS conflict-free (warp = 32 consecutive p, same channel) ----
    const float* xin = x + (size_t)ba * CH * P + p0;
    #pragma unroll
    for (int k = 0; k < 22; k++) {
        const int idx = t + k * NT;                   // need < 5440
        if (k < 21 || idx < CH * TP) {
            const int c = idx >> 6;                   // channel
            const int p = idx & 63;                   // position
            tile[c * PITCH + p] = ld_ef(xin + (size_t)c * P + p, pol_ef);
        }
    }
    __syncthreads();

    // ---- cls: output-linear; tile region = 1280 contiguous float4.
    //      thread t writes f = t + 256k -> warp STG.128 = 512B contig
    //      = 4 L2 line-touches. ----
    {
        float4* ocls4 = reinterpret_cast<float4*>(
            out + CLS_OFF + (size_t)(ba * P + p0) * 80);
        #pragma unroll
        for (int k = 0; k < 5; k++) {
            const int f = t + k * NT;                 // 0..1279
            const int p = f / 20;                     // position in tile (0..63)
            const int j = f - 20 * p;                 // float4 chunk (0..19)
            const int c = 5 + 4 * j;                  // channels c..c+3
            float4 o;
            o.x = sigf(tile[(c + 0) * PITCH + p]);
            o.y = sigf(tile[(c + 1) * PITCH + p]);
            o.z = sigf(tile[(c + 2) * PITCH + p]);
            o.w = sigf(tile[(c + 3) * PITCH + p]);
            st_el4(ocls4 + f, o, pol_el);
        }
    }

    // ---- boxes: threads 0..63, STG.128; warp = 512B contiguous ----
    if (t < TP) {
        const int a  = ba - (ba / A) * A;
        const float aw = __ldg(anchors + a * 2 + 0);
        const float ah = __ldg(anchors + a * 2 + 1);
        const int pg = p0 + t;
        float4 b;
        b.x = (sigf(tile[0 * PITCH + t]) + (float)(pg >> 6)) * (1.0f / 64.0f);
        b.y = (sigf(tile[1 * PITCH + t]) + (float)(pg & 63)) * (1.0f / 64.0f);
        b.z = __expf(tile[2 * PITCH + t]) * aw;
        b.w = __expf(tile[3 * PITCH + t]) * ah;
        st_el4(reinterpret_cast<float4*>(out) + ba * P + pg, b, pol_el);
    }
    // ---- conf: threads 64..79, 4 scalar LDS + hinted STG.128 ----
    else if (t < TP + TP / 4) {
        const int q = t - TP;                         // 0..15
        float4 v;
        v.x = sigf(tile[4 * PITCH + 4 * q + 0]);
        v.y = sigf(tile[4 * PITCH + 4 * q + 1]);
        v.z = sigf(tile[4 * PITCH + 4 * q + 2]);
        v.w = sigf(tile[4 * PITCH + 4 * q + 3]);
        st_el4(reinterpret_cast<float4*>(out + CONF_OFF + ba * P + p0) + q,
               v, pol_el);
    }
}

extern "C" void kernel_launch(void* const* d_in, const int* in_sizes, int n_in,
                              void* d_out, int out_size) {
    const float* x       = (const float*)d_in[0];
    const float* anchors = (const float*)d_in[1];
    float*       out     = (float*)d_out;
    yolo_kernel<<<3072, NT>>>(x, anchors, out);
}